// round 6
// baseline (speedup 1.0000x reference)
#include <cuda_runtime.h>
#include <cstdint>

// ---------------- problem dims ----------------
static constexpr int NE   = 8;
static constexpr int TOKN = 1024;
static constexpr int HID  = 2048;
static constexpr int ITR  = 6144;

static constexpr int BM = 128;   // CTA M tile
static constexpr int BK = 32;    // K chunk per stage

// padded fragment-layout strides (floats) - chosen for low STS conflicts
static constexpr int ASTR = 136; // per (ks,mrow16) block: 32 lanes * 4 words + 8 pad
static constexpr int BSTR = 66;  // per (ks,nj8) block:    32 lanes * 2 words + 2 pad

// fp32 intermediate activations (no cudaMalloc allowed -> static device scratch)
__device__ float g_hidden[(size_t)NE * TOKN * ITR];

// ---------------- ptx helpers (baseline PTX only) ----------------
__device__ __forceinline__ uint32_t f2tf(float f) {
    uint32_t r;
    asm("cvt.rna.tf32.f32 %0, %1;\n" : "=r"(r) : "f"(f));
    return r;
}
// D += A*B, m16n8k8 tf32 (A row-major frag, B col-major frag)
__device__ __forceinline__ void mma_tf32(float* c, const uint32_t* a, const uint32_t* b) {
    asm volatile(
        "mma.sync.aligned.m16n8k8.row.col.f32.tf32.tf32.f32 "
        "{%0,%1,%2,%3}, {%4,%5,%6,%7}, {%8,%9}, {%0,%1,%2,%3};\n"
        : "+f"(c[0]), "+f"(c[1]), "+f"(c[2]), "+f"(c[3])
        : "r"(a[0]), "r"(a[1]), "r"(a[2]), "r"(a[3]), "r"(b[0]), "r"(b[1]));
}

// ---------------- GEMM kernel ----------------
// D[M,N] = A[M,K] * B[K,N].  A K-contiguous, B N-contiguous (row-major [K,N]).
// SMEM holds tiles pre-converted to tf32 and pre-shuffled into mma fragment
// order, so the inner loop is pure {LDS.128/LDS.64 + HMMA}.
// FUSED: two B streams (gate @ n0, up @ n0+ITR), epilogue = silu(gate)*up.
template <int BNS, bool FUSED>
__global__ __launch_bounds__(256, 2)
void moe_mma_kernel(const float* __restrict__ Ag,
                    const float* __restrict__ Bg,
                    float* __restrict__ Og,
                    int K, int bstride, int ostride, int kiter) {
    constexpr int NSTR = FUSED ? 2 : 1;
    constexpr int NJT  = BNS / 8;        // 8-col tiles per stream
    constexpr int NJ   = NJT / 2;        // per warp (split by wn)
    constexpr int NBB  = BNS / 32;       // B float4 loads per thread per stream
    constexpr int ASZ  = 4 * 8 * ASTR;   // 4 ks * 8 mrow blocks
    constexpr int BSZ  = 4 * NJT * BSTR;

    __shared__ uint32_t Asm[ASZ];
    __shared__ uint32_t Bsm[NSTR][BSZ];

    const int tid  = threadIdx.x;
    const int wid  = tid >> 5, lane = tid & 31;
    const int wm   = wid >> 1, wn = wid & 1;

    const int e  = blockIdx.z;
    const int m0 = blockIdx.y * BM;
    const int n0 = blockIdx.x * BNS;

    const float* A  = Ag + ((size_t)e * TOKN + m0) * K;
    const float* B0 = Bg + (size_t)e * K * bstride + n0;
    float*       O  = Og + ((size_t)e * TOKN + m0) * ostride + n0;

    // ---- staging maps (constant per thread) ----
    // A tile 128x32: thread handles float4 q = tid + 256*i, i<4.
    int aoff[4];     // gmem float offset within tile
    uint32_t sA[4];  // smem uint index of word j=0 (j advances +4)
#pragma unroll
    for (int i = 0; i < 4; ++i) {
        int q = tid + 256 * i;
        int r = q >> 3, c4 = (q & 7) * 4;
        aoff[i] = r * K + c4;
        int ks = c4 >> 3, half = (c4 >> 2) & 1;
        int mrow = r >> 4, gg = r & 7, hi = (r >> 3) & 1;
        sA[i] = (uint32_t)((ks * 8 + mrow) * ASTR + gg * 16 + half * 2 + hi);
    }
    // B tile 32xBNS per stream: thread handles float4 q = tid + 256*i, i<NBB.
    int boff[NBB];
    uint32_t sB[NBB];
#pragma unroll
    for (int i = 0; i < NBB; ++i) {
        int q = tid + 256 * i;
        int r = q / (BNS / 4), c4 = (q % (BNS / 4)) * 4;
        boff[i] = r * bstride + c4;
        int ks = r >> 3, kk = r & 7, tt = kk & 3, half = kk >> 2;
        int njb = c4 >> 3, gb = c4 & 7;
        sB[i] = (uint32_t)((ks * NJT + njb) * BSTR + (gb * 4 + tt) * 2 + half);
    }

    // ---- register prefetch buffers ----
    float4 rA[4];
    float4 rB[NSTR][NBB];

    auto ldg = [&](int kc) {
        const float* Ab = A + (size_t)kc * BK;
#pragma unroll
        for (int i = 0; i < 4; ++i)
            rA[i] = *reinterpret_cast<const float4*>(Ab + aoff[i]);
        const float* Bb = B0 + (size_t)kc * BK * bstride;
#pragma unroll
        for (int s = 0; s < NSTR; ++s) {
            const float* Bs_ = Bb + (FUSED ? s * ITR : 0);
#pragma unroll
            for (int i = 0; i < NBB; ++i)
                rB[s][i] = *reinterpret_cast<const float4*>(Bs_ + boff[i]);
        }
    };

    auto sts = [&]() {
#pragma unroll
        for (int i = 0; i < 4; ++i) {
            const float* v = reinterpret_cast<const float*>(&rA[i]);
#pragma unroll
            for (int j = 0; j < 4; ++j)
                Asm[sA[i] + j * 4] = f2tf(v[j]);
        }
#pragma unroll
        for (int s = 0; s < NSTR; ++s)
#pragma unroll
            for (int i = 0; i < NBB; ++i) {
                const float* v = reinterpret_cast<const float*>(&rB[s][i]);
#pragma unroll
                for (int j = 0; j < 4; ++j)
                    Bsm[s][sB[i] + j * 8] = f2tf(v[j]);
            }
    };

    float acc[NSTR][2][NJ][4] = {};

    // ---- pipeline: regs hold chunk c during compute of chunk c-1 ----
    ldg(0);
    for (int c = 0; c < kiter; ++c) {
        sts();
        __syncthreads();
        if (c + 1 < kiter) ldg(c + 1);

#pragma unroll
        for (int ks = 0; ks < 4; ++ks) {
            uint32_t af[2][4];
#pragma unroll
            for (int mi = 0; mi < 2; ++mi) {
                uint4 v = *reinterpret_cast<const uint4*>(
                    &Asm[(ks * 8 + wm * 2 + mi) * ASTR + lane * 4]);
                af[mi][0] = v.x; af[mi][1] = v.y; af[mi][2] = v.z; af[mi][3] = v.w;
            }
#pragma unroll
            for (int s = 0; s < NSTR; ++s)
#pragma unroll
                for (int nj = 0; nj < NJ; ++nj) {
                    uint2 b = *reinterpret_cast<const uint2*>(
                        &Bsm[s][(ks * NJT + wn * NJ + nj) * BSTR + lane * 2]);
                    uint32_t bf[2] = {b.x, b.y};
                    mma_tf32(acc[s][0][nj], af[0], bf);
                    mma_tf32(acc[s][1][nj], af[1], bf);
                }
        }
        __syncthreads();
    }

    // ---- epilogue ----
    const int g = lane >> 2, t = lane & 3;
#pragma unroll
    for (int mi = 0; mi < 2; ++mi) {
#pragma unroll
        for (int h = 0; h < 2; ++h) {
            const int row = wm * 32 + mi * 16 + g + h * 8;
            float* orow = O + (size_t)row * ostride + wn * (BNS / 2);
#pragma unroll
            for (int nj = 0; nj < NJ; ++nj) {
                const int col = nj * 8 + 2 * t;
                float2 v;
                if (FUSED) {
                    float g0 = acc[0][mi][nj][2 * h],     u0 = acc[1][mi][nj][2 * h];
                    float g1 = acc[0][mi][nj][2 * h + 1], u1 = acc[1][mi][nj][2 * h + 1];
                    v.x = g0 / (1.0f + __expf(-g0)) * u0;   // silu(gate)*up
                    v.y = g1 / (1.0f + __expf(-g1)) * u1;
                } else {
                    v.x = acc[0][mi][nj][2 * h];
                    v.y = acc[0][mi][nj][2 * h + 1];
                }
                *reinterpret_cast<float2*>(orow + col) = v;
            }
        }
    }
}

// ---------------- launch ----------------
extern "C" void kernel_launch(void* const* d_in, const int* in_sizes, int n_in,
                              void* d_out, int out_size) {
    (void)in_sizes; (void)n_in; (void)out_size;
    const float* x   = (const float*)d_in[0];   // [E*T, D]
    const float* wgu = (const float*)d_in[1];   // [E, D, 2I]
    const float* wdn = (const float*)d_in[2];   // [E, I, D]
    float* out = (float*)d_out;                 // [E*T, D]

    float* hid = nullptr;
    cudaGetSymbolAddress((void**)&hid, g_hidden);

    // stage 1: gate_up GEMM + silu*up fused epilogue -> g_hidden [E,T,I]
    moe_mma_kernel<64, true><<<dim3(ITR / 64, TOKN / BM, NE), 256>>>(
        x, wgu, hid, HID, 2 * ITR, ITR, HID / BK);
    // stage 2: down GEMM -> out [E,T,D]
    moe_mma_kernel<128, false><<<dim3(HID / 128, TOKN / BM, NE), 256>>>(
        hid, wdn, out, ITR, HID, HID, ITR / BK);
}